// round 4
// baseline (speedup 1.0000x reference)
#include <cuda_runtime.h>
#include <cstdint>
#include <cstddef>

#define NN   8192
#define DF   784
#define DEMB 256
#define TK   11
#define TK2  16    // coarse candidate count (margin >> coarse error)

// ---------------- scratch (static device globals; no allocs) ----------------
__device__ float g_sq[NN];                // correctly-rounded fp32 row norms
__device__ int   g_idx16[NN * TK2];       // coarse candidates
__device__ int   g_idx[NN * TK];          // refined top-11 (matches ref ordering)
__device__ int   g_cnt[NN];
__device__ float g_dv[NN];
__device__ float g_G[(size_t)NN * DF];    // gathered dv-weighted rows

// ---------------- 1. row squared norms (correctly rounded) ----------------
// Kahan per-lane (intrinsics block FMA contraction) + double tree reduce.
__global__ void sq_kernel(const float* __restrict__ X) {
    int row  = blockIdx.x * 8 + (threadIdx.x >> 5);
    int lane = threadIdx.x & 31;
    const float* xr = X + (size_t)row * DF;
    float s = 0.f, c = 0.f;
    for (int k = lane; k < DF; k += 32) {
        float v = xr[k];
        float p = __fmul_rn(v, v);
        float y = __fsub_rn(p, c);
        float t = __fadd_rn(s, y);
        c = __fsub_rn(__fsub_rn(t, s), y);
        s = t;
    }
    double d = (double)s + (double)c;
    #pragma unroll
    for (int o = 16; o; o >>= 1) d += __shfl_xor_sync(0xffffffffu, d, o);
    if (lane == 0) g_sq[row] = (float)d;
}

// ---------------- 2. coarse dist GEMM: D[i][j] ~= |sq_i + sq_j - 2 x_i.x_j| ----------------
#define BM 128
#define BN 128
#define BK 16
#define SPAD 4

__global__ __launch_bounds__(256) void dist_gemm(const float* __restrict__ X,
                                                 float* __restrict__ D) {
    __shared__ float As[BK][BM + SPAD];
    __shared__ float Bs[BK][BN + SPAD];
    int tid = threadIdx.x;
    int tx = tid & 15, ty = tid >> 4;
    int bi = blockIdx.y * BM, bj = blockIdx.x * BN;

    float acc[8][8];
    #pragma unroll
    for (int m = 0; m < 8; m++)
        #pragma unroll
        for (int n = 0; n < 8; n++) acc[m][n] = 0.f;

    for (int k0 = 0; k0 < DF; k0 += BK) {
        #pragma unroll
        for (int l = 0; l < 2; l++) {
            int q = tid + l * 256;
            int row = q >> 2, c4 = (q & 3) * 4;
            float4 v = *reinterpret_cast<const float4*>(X + (size_t)(bi + row) * DF + k0 + c4);
            As[c4 + 0][row] = v.x; As[c4 + 1][row] = v.y;
            As[c4 + 2][row] = v.z; As[c4 + 3][row] = v.w;
            float4 w = *reinterpret_cast<const float4*>(X + (size_t)(bj + row) * DF + k0 + c4);
            Bs[c4 + 0][row] = w.x; Bs[c4 + 1][row] = w.y;
            Bs[c4 + 2][row] = w.z; Bs[c4 + 3][row] = w.w;
        }
        __syncthreads();
        #pragma unroll
        for (int kk = 0; kk < BK; kk++) {
            float a[8], b[8];
            #pragma unroll
            for (int m = 0; m < 8; m++) a[m] = As[kk][ty * 8 + m];
            #pragma unroll
            for (int n = 0; n < 8; n++) b[n] = Bs[kk][tx * 8 + n];
            #pragma unroll
            for (int m = 0; m < 8; m++)
                #pragma unroll
                for (int n = 0; n < 8; n++) acc[m][n] = fmaf(a[m], b[n], acc[m][n]);
        }
        __syncthreads();
    }

    float sqi[8], sqj[8];
    #pragma unroll
    for (int m = 0; m < 8; m++) sqi[m] = g_sq[bi + ty * 8 + m];
    #pragma unroll
    for (int n = 0; n < 8; n++) sqj[n] = g_sq[bj + tx * 8 + n];
    #pragma unroll
    for (int m = 0; m < 8; m++) {
        int i = bi + ty * 8 + m;
        #pragma unroll
        for (int n = 0; n < 8; n += 4) {
            float4 o;
            o.x = fabsf(sqi[m] + sqj[n + 0] - 2.f * acc[m][n + 0]);
            o.y = fabsf(sqi[m] + sqj[n + 1] - 2.f * acc[m][n + 1]);
            o.z = fabsf(sqi[m] + sqj[n + 2] - 2.f * acc[m][n + 2]);
            o.w = fabsf(sqi[m] + sqj[n + 3] - 2.f * acc[m][n + 3]);
            *reinterpret_cast<float4*>(D + (size_t)i * NN + bj + tx * 8 + n) = o;
        }
    }
}

// ---------------- 3. per-row coarse top-16 (stable keys: dist_bits<<32 | idx) ----------------
__global__ __launch_bounds__(256) void topk16_kernel(const float* __restrict__ D) {
    int row = blockIdx.x;
    int t = threadIdx.x;
    int lane = t & 31, wid = t >> 5;
    const float* dr = D + (size_t)row * NN;

    unsigned long long loc[TK2];
    #pragma unroll
    for (int k = 0; k < TK2; k++) loc[k] = ~0ull;

    for (int j = t; j < NN; j += 256) {
        unsigned long long key =
            ((unsigned long long)__float_as_uint(dr[j]) << 32) | (unsigned)j;
        if (key < loc[TK2 - 1]) {
            unsigned long long v = key;
            #pragma unroll
            for (int k = 0; k < TK2; k++) {
                unsigned long long cur = loc[k];
                if (v < cur) { loc[k] = v; v = cur; }
            }
        }
    }

    __shared__ unsigned long long sh[256 * TK2];
    __shared__ unsigned long long warpmin[8];
    __shared__ unsigned long long gmin;
    #pragma unroll
    for (int k = 0; k < TK2; k++) sh[t * TK2 + k] = loc[k];

    int p = 0;
    for (int out = 0; out < TK2; out++) {
        unsigned long long m = (p < TK2) ? sh[t * TK2 + p] : ~0ull;
        #pragma unroll
        for (int o = 16; o; o >>= 1) {
            unsigned long long other = __shfl_xor_sync(0xffffffffu, m, o);
            if (other < m) m = other;
        }
        if (lane == 0) warpmin[wid] = m;
        __syncthreads();
        if (t == 0) {
            unsigned long long g = warpmin[0];
            #pragma unroll
            for (int w = 1; w < 8; w++) if (warpmin[w] < g) g = warpmin[w];
            gmin = g;
            g_idx16[row * TK2 + out] = (int)(unsigned)g;
        }
        __syncthreads();
        unsigned long long g = gmin;
        if (p < TK2 && sh[t * TK2 + p] == g) p++;   // keys unique
    }
}

// ---------------- 4. refine: exact dists with ref's rounding chain, pick top-11 ----------------
__global__ __launch_bounds__(128) void refine_kernel(const float* __restrict__ X) {
    int row = blockIdx.x;
    int wid = threadIdx.x >> 5, lane = threadIdx.x & 31;
    __shared__ unsigned long long keys[TK2];
    __shared__ int cand[TK2];
    if (threadIdx.x < TK2) cand[threadIdx.x] = g_idx16[row * TK2 + threadIdx.x];
    __syncthreads();

    float sqi = g_sq[row];
    const float* xi = X + (size_t)row * DF;

    for (int k4 = wid; k4 < TK2; k4 += 4) {
        int j = cand[k4];
        const float* xj = X + (size_t)j * DF;
        // Kahan fp32 dot (no FMA contraction), exact to ~1e-6
        float s = 0.f, c = 0.f;
        for (int k = lane; k < DF; k += 32) {
            float p = __fmul_rn(xi[k], xj[k]);
            float y = __fsub_rn(p, c);
            float t = __fadd_rn(s, y);
            c = __fsub_rn(__fsub_rn(t, s), y);
            s = t;
        }
        double d = (double)s + (double)c;
        #pragma unroll
        for (int o = 16; o; o >>= 1) d += __shfl_xor_sync(0xffffffffu, d, o);
        if (lane == 0) {
            float dotf = (float)d;                          // fl32(exact dot)
            float t1 = __fadd_rn(sqi, g_sq[j]);             // fl32(sq_i + sq_j)
            float t3 = fabsf(__fsub_rn(t1, __fmul_rn(2.0f, dotf)));  // fl32(t1 - 2dot)
            keys[k4] = ((unsigned long long)__float_as_uint(t3) << 32) | (unsigned)j;
        }
    }
    __syncthreads();

    if (threadIdx.x == 0) {
        unsigned long long a[TK2];
        #pragma unroll
        for (int i = 0; i < TK2; i++) a[i] = keys[i];
        #pragma unroll
        for (int i = 1; i < TK2; i++) {      // insertion sort ascending
            unsigned long long v = a[i];
            int k = i - 1;
            while (k >= 0 && a[k] > v) { a[k + 1] = a[k]; k--; }
            a[k + 1] = v;
        }
        #pragma unroll
        for (int k = 0; k < TK; k++) g_idx[row * TK + k] = (int)(unsigned)a[k];
    }
}

// ---------------- 5. vertex degrees ----------------
__global__ void zero_cnt() {
    int t = blockIdx.x * 256 + threadIdx.x;
    if (t < NN) g_cnt[t] = 0;
}
__global__ void count_kernel() {
    int t = blockIdx.x * 256 + threadIdx.x;
    if (t < NN * TK) atomicAdd(&g_cnt[g_idx[t]], 1);
}
__global__ void dv_kernel() {
    int t = blockIdx.x * 256 + threadIdx.x;
    if (t < NN) g_dv[t] = 1.0f / sqrtf((float)g_cnt[t]);
}

// ---------------- zero fill ----------------
__global__ void zero_kernel(float4* __restrict__ p, size_t n4) {
    size_t t = (size_t)blockIdx.x * blockDim.x + threadIdx.x;
    size_t stride = (size_t)gridDim.x * blockDim.x;
    float4 z = make_float4(0.f, 0.f, 0.f, 0.f);
    for (size_t i = t; i < n4; i += stride) p[i] = z;
}

// ---------------- 6. H scatter: H[idx[i][k]][i] = 1 ----------------
__global__ void scatterH(float* __restrict__ H) {
    int t = blockIdx.x * 256 + threadIdx.x;
    if (t < NN * TK) {
        int i = t / TK;
        int r = g_idx[t];
        H[(size_t)r * NN + i] = 1.0f;
    }
}

// ---------------- 7. gather: G[i] = sum_k dv[idx]*X[idx] ----------------
__global__ __launch_bounds__(256) void gather_kernel(const float* __restrict__ X) {
    int i = blockIdx.x;
    __shared__ int   sidx[TK];
    __shared__ float sdv[TK];
    if (threadIdx.x < TK) {
        int r = g_idx[i * TK + threadIdx.x];
        sidx[threadIdx.x] = r;
        sdv[threadIdx.x]  = g_dv[r];
    }
    __syncthreads();
    for (int c = threadIdx.x; c < DF; c += 256) {
        float s = 0.f;
        #pragma unroll
        for (int k = 0; k < TK; k++)
            s = fmaf(sdv[k], X[(size_t)sidx[k] * DF + c], s);
        g_G[(size_t)i * DF + c] = s;
    }
}

// ---------------- 8. X_out = de * G @ theta   (M=8192, N=256, K=784) ----------------
__global__ __launch_bounds__(256) void out_gemm(const float* __restrict__ theta,
                                                float* __restrict__ Xout) {
    __shared__ float As[BK][64 + SPAD];
    __shared__ float Bs[BK][64 + SPAD];
    int tid = threadIdx.x;
    int tx = tid & 15, ty = tid >> 4;
    int bi = blockIdx.y * 64, bj = blockIdx.x * 64;

    float acc[4][4];
    #pragma unroll
    for (int m = 0; m < 4; m++)
        #pragma unroll
        for (int n = 0; n < 4; n++) acc[m][n] = 0.f;

    for (int k0 = 0; k0 < DF; k0 += BK) {
        {
            int row = tid >> 2, c4 = (tid & 3) * 4;
            float4 v = *reinterpret_cast<const float4*>(g_G + (size_t)(bi + row) * DF + k0 + c4);
            As[c4 + 0][row] = v.x; As[c4 + 1][row] = v.y;
            As[c4 + 2][row] = v.z; As[c4 + 3][row] = v.w;
            int kr = tid >> 4, n4 = (tid & 15) * 4;
            float4 w = *reinterpret_cast<const float4*>(theta + (size_t)(k0 + kr) * DEMB + bj + n4);
            Bs[kr][n4 + 0] = w.x; Bs[kr][n4 + 1] = w.y;
            Bs[kr][n4 + 2] = w.z; Bs[kr][n4 + 3] = w.w;
        }
        __syncthreads();
        #pragma unroll
        for (int kk = 0; kk < BK; kk++) {
            float a[4], b[4];
            #pragma unroll
            for (int m = 0; m < 4; m++) a[m] = As[kk][ty * 4 + m];
            #pragma unroll
            for (int n = 0; n < 4; n++) b[n] = Bs[kk][tx * 4 + n];
            #pragma unroll
            for (int m = 0; m < 4; m++)
                #pragma unroll
                for (int n = 0; n < 4; n++) acc[m][n] = fmaf(a[m], b[n], acc[m][n]);
        }
        __syncthreads();
    }
    const float de = 0.30151134457776363f;  // 11^-0.5
    #pragma unroll
    for (int m = 0; m < 4; m++) {
        int i = bi + ty * 4 + m;
        float4 o;
        o.x = de * acc[m][0]; o.y = de * acc[m][1];
        o.z = de * acc[m][2]; o.w = de * acc[m][3];
        *reinterpret_cast<float4*>(Xout + (size_t)i * DEMB + bj + tx * 4) = o;
    }
}

// ---------------- 9. E = dv * de * scatter-add of X_out ----------------
__global__ void scatterE(const float* __restrict__ Xout, float* __restrict__ E) {
    int j = blockIdx.x;
    int c = threadIdx.x;
    float v = Xout[(size_t)j * DEMB + c];
    #pragma unroll
    for (int k = 0; k < TK; k++) {
        int r = __ldg(&g_idx[j * TK + k]);
        atomicAdd(E + (size_t)r * DEMB + c, v);
    }
}
__global__ void scaleE(float* __restrict__ E) {
    int t = blockIdx.x * 256 + threadIdx.x;
    const float de = 0.30151134457776363f;
    int i = t >> 8;
    E[t] *= g_dv[i] * de;
}

// ---------------- launch ----------------
extern "C" void kernel_launch(void* const* d_in, const int* in_sizes, int n_in,
                              void* d_out, int out_size) {
    const float* X     = (const float*)d_in[0];
    const float* theta = (const float*)d_in[1];
    float* out  = (float*)d_out;
    float* Xout = out;                                // [8192, 256]
    float* E    = out + (size_t)NN * DEMB;            // [8192, 256]
    float* H    = out + 2 * (size_t)NN * DEMB;        // [8192, 8192] (dist scratch first)

    sq_kernel<<<NN / 8, 256>>>(X);
    dist_gemm<<<dim3(NN / BN, NN / BM), 256>>>(X, H);     // coarse dist into H region
    topk16_kernel<<<NN, 256>>>(H);
    refine_kernel<<<NN, 128>>>(X);                        // exact-emulated top-11
    zero_cnt<<<NN / 256, 256>>>();
    count_kernel<<<(NN * TK + 255) / 256, 256>>>();
    dv_kernel<<<NN / 256, 256>>>();
    zero_kernel<<<2048, 256>>>((float4*)H, (size_t)NN * NN / 4);
    scatterH<<<(NN * TK + 255) / 256, 256>>>(H);
    gather_kernel<<<NN, 256>>>(X);
    out_gemm<<<dim3(DEMB / 64, NN / 64), 256>>>(theta, Xout);
    zero_kernel<<<256, 256>>>((float4*)E, (size_t)NN * DEMB / 4);
    scatterE<<<NN, 256>>>(Xout, E);
    scaleE<<<NN * DEMB / 256, 256>>>(E);
}

// round 7
// speedup vs baseline: 1.9980x; 1.9980x over previous
#include <cuda_runtime.h>
#include <cuda_bf16.h>
#include <cstdint>
#include <cstddef>

#define NN   8192
#define DF   784
#define DFP  800     // padded K (25 * 32)
#define DEMB 256
#define TK   11
#define TK2  24      // coarse candidate count (margin >> bf16 coarse error)

// ---------------- scratch (static device globals; no allocs) ----------------
__device__ float g_sq[NN];                            // correctly-rounded fp32 row norms
__device__ __align__(16) __nv_bfloat16 g_Xb[(size_t)NN * DFP];  // bf16 X, zero-padded
__device__ int   g_idx24[NN * TK2];                   // coarse candidates
__device__ int   g_idx[NN * TK];                      // refined top-11
__device__ int   g_cnt[NN];
__device__ float g_dv[NN];
__device__ float g_G[(size_t)NN * DF];                // gathered dv-weighted rows

__device__ __forceinline__ unsigned smem_u32(const void* p) {
    return (unsigned)__cvta_generic_to_shared(p);
}

// ---------------- 0. convert X -> bf16 (zero-pad K to 800) ----------------
__global__ void conv_kernel(const float* __restrict__ X) {
    int row = blockIdx.x;
    for (int c = threadIdx.x; c < DFP; c += 256) {
        g_Xb[(size_t)row * DFP + c] =
            (c < DF) ? __float2bfloat16_rn(X[(size_t)row * DF + c]) : __float2bfloat16_rn(0.f);
    }
}

// ---------------- 1. row squared norms (correctly rounded) ----------------
__global__ void sq_kernel(const float* __restrict__ X) {
    int row  = blockIdx.x * 8 + (threadIdx.x >> 5);
    int lane = threadIdx.x & 31;
    const float* xr = X + (size_t)row * DF;
    float s = 0.f, c = 0.f;
    for (int k = lane; k < DF; k += 32) {
        float v = xr[k];
        float p = __fmul_rn(v, v);
        float y = __fsub_rn(p, c);
        float t = __fadd_rn(s, y);
        c = __fsub_rn(__fsub_rn(t, s), y);
        s = t;
    }
    double d = (double)s + (double)c;
    #pragma unroll
    for (int o = 16; o; o >>= 1) d += __shfl_xor_sync(0xffffffffu, d, o);
    if (lane == 0) g_sq[row] = (float)d;
}

// ---------------- 2. coarse dist via bf16 tensor cores ----------------
// C = Xb @ Xb^T ; D[i][j] = |sq_i + sq_j - 2 C[i][j]|
// block 128x128, BK=32, 8 warps of 64x32; mma.sync m16n8k16 bf16->f32
#define SROW 40   // smem row stride in bf16 elems (80 B -> conflict-free ldmatrix)

__global__ __launch_bounds__(256) void dist_mma(float* __restrict__ D) {
    __shared__ __nv_bfloat16 As[128 * SROW];
    __shared__ __nv_bfloat16 Bs[128 * SROW];

    int tid  = threadIdx.x;
    int warp = tid >> 5, lane = tid & 31;
    int bi = blockIdx.y * 128, bj = blockIdx.x * 128;
    int wm = (warp >> 2) * 64;     // 0 / 64
    int wn = (warp & 3) * 32;      // 0 / 32 / 64 / 96

    float acc[4][4][4];
    #pragma unroll
    for (int m = 0; m < 4; m++)
        #pragma unroll
        for (int n = 0; n < 4; n++)
            #pragma unroll
            for (int r = 0; r < 4; r++) acc[m][n][r] = 0.f;

    for (int kt = 0; kt < DFP / 32; kt++) {
        // load 128x32 bf16 tiles of A and B (each row = 4 x int4)
        #pragma unroll
        for (int l = 0; l < 2; l++) {
            int q = tid + l * 256;
            int row = q >> 2, ch = q & 3;
            const int4* sa = (const int4*)(g_Xb + (size_t)(bi + row) * DFP + kt * 32 + ch * 8);
            *(int4*)(As + row * SROW + ch * 8) = *sa;
            const int4* sb = (const int4*)(g_Xb + (size_t)(bj + row) * DFP + kt * 32 + ch * 8);
            *(int4*)(Bs + row * SROW + ch * 8) = *sb;
        }
        __syncthreads();

        #pragma unroll
        for (int ks = 0; ks < 2; ks++) {
            int k0 = ks * 16;
            // A fragments: 4 m-tiles of 16 rows
            uint32_t a[4][4];
            #pragma unroll
            for (int mt = 0; mt < 4; mt++) {
                unsigned ad = smem_u32(As + (wm + mt * 16 + (lane & 15)) * SROW
                                          + k0 + ((lane >> 4) << 3));
                asm volatile("ldmatrix.sync.aligned.m8n8.x4.shared.b16 {%0,%1,%2,%3}, [%4];"
                             : "=r"(a[mt][0]), "=r"(a[mt][1]), "=r"(a[mt][2]), "=r"(a[mt][3])
                             : "r"(ad));
            }
            // B fragments: 4 n-tiles of 8 (two x4 loads, 16 n each)
            uint32_t b[4][2];
            #pragma unroll
            for (int bt = 0; bt < 2; bt++) {
                int nloc = wn + bt * 16 + ((lane >> 4) << 3) + (lane & 7);
                unsigned ad = smem_u32(Bs + nloc * SROW + k0 + (((lane >> 3) & 1) << 3));
                uint32_t r0, r1, r2, r3;
                asm volatile("ldmatrix.sync.aligned.m8n8.x4.shared.b16 {%0,%1,%2,%3}, [%4];"
                             : "=r"(r0), "=r"(r1), "=r"(r2), "=r"(r3) : "r"(ad));
                b[2 * bt][0] = r0; b[2 * bt][1] = r1;
                b[2 * bt + 1][0] = r2; b[2 * bt + 1][1] = r3;
            }
            #pragma unroll
            for (int mt = 0; mt < 4; mt++)
                #pragma unroll
                for (int nt = 0; nt < 4; nt++) {
                    asm volatile(
                        "mma.sync.aligned.m16n8k16.row.col.f32.bf16.bf16.f32 "
                        "{%0,%1,%2,%3}, {%4,%5,%6,%7}, {%8,%9}, {%0,%1,%2,%3};"
                        : "+f"(acc[mt][nt][0]), "+f"(acc[mt][nt][1]),
                          "+f"(acc[mt][nt][2]), "+f"(acc[mt][nt][3])
                        : "r"(a[mt][0]), "r"(a[mt][1]), "r"(a[mt][2]), "r"(a[mt][3]),
                          "r"(b[nt][0]), "r"(b[nt][1]));
                }
        }
        __syncthreads();
    }

    // epilogue: dist = |sq_i + sq_j - 2*acc|
    int r_in = lane >> 2, cb = (lane & 3) * 2;
    #pragma unroll
    for (int mt = 0; mt < 4; mt++) {
        #pragma unroll
        for (int half = 0; half < 2; half++) {
            int gi = bi + wm + mt * 16 + r_in + half * 8;
            float sqi = g_sq[gi];
            #pragma unroll
            for (int nt = 0; nt < 4; nt++) {
                int gj = bj + wn + nt * 8 + cb;
                float2 o;
                o.x = fabsf(sqi + g_sq[gj]     - 2.f * acc[mt][nt][half * 2 + 0]);
                o.y = fabsf(sqi + g_sq[gj + 1] - 2.f * acc[mt][nt][half * 2 + 1]);
                *reinterpret_cast<float2*>(D + (size_t)gi * NN + gj) = o;
            }
        }
    }
}

// ---------------- 3. per-row coarse top-24 (stable keys: dist_bits<<32 | idx) ----------------
__global__ __launch_bounds__(128) void topk24_kernel(const float* __restrict__ D) {
    int row = blockIdx.x;
    int t = threadIdx.x;
    int lane = t & 31, wid = t >> 5;
    const float* dr = D + (size_t)row * NN;

    unsigned long long loc[TK2];
    #pragma unroll
    for (int k = 0; k < TK2; k++) loc[k] = ~0ull;

    for (int j = t; j < NN; j += 128) {
        unsigned long long key =
            ((unsigned long long)__float_as_uint(dr[j]) << 32) | (unsigned)j;
        if (key < loc[TK2 - 1]) {
            unsigned long long v = key;
            #pragma unroll
            for (int k = 0; k < TK2; k++) {
                unsigned long long cur = loc[k];
                if (v < cur) { loc[k] = v; v = cur; }
            }
        }
    }

    __shared__ unsigned long long sh[128 * TK2];
    __shared__ unsigned long long warpmin[4];
    __shared__ unsigned long long gmin;
    #pragma unroll
    for (int k = 0; k < TK2; k++) sh[t * TK2 + k] = loc[k];

    int p = 0;
    for (int out = 0; out < TK2; out++) {
        unsigned long long m = (p < TK2) ? sh[t * TK2 + p] : ~0ull;
        #pragma unroll
        for (int o = 16; o; o >>= 1) {
            unsigned long long other = __shfl_xor_sync(0xffffffffu, m, o);
            if (other < m) m = other;
        }
        if (lane == 0) warpmin[wid] = m;
        __syncthreads();
        if (t == 0) {
            unsigned long long g = warpmin[0];
            #pragma unroll
            for (int w = 1; w < 4; w++) if (warpmin[w] < g) g = warpmin[w];
            gmin = g;
            g_idx24[row * TK2 + out] = (int)(unsigned)g;
        }
        __syncthreads();
        unsigned long long g = gmin;
        if (p < TK2 && sh[t * TK2 + p] == g) p++;   // keys unique
    }
}

// ---------------- 4. refine: exact dists with ref's rounding chain, pick top-11 ----------------
__global__ __launch_bounds__(128) void refine_kernel(const float* __restrict__ X) {
    int row = blockIdx.x;
    int wid = threadIdx.x >> 5, lane = threadIdx.x & 31;
    __shared__ unsigned long long keys[TK2];
    __shared__ int cand[TK2];
    if (threadIdx.x < TK2) cand[threadIdx.x] = g_idx24[row * TK2 + threadIdx.x];
    __syncthreads();

    float sqi = g_sq[row];
    const float* xi = X + (size_t)row * DF;

    for (int k4 = wid; k4 < TK2; k4 += 4) {
        int j = cand[k4];
        const float* xj = X + (size_t)j * DF;
        float s = 0.f, c = 0.f;
        for (int k = lane; k < DF; k += 32) {
            float p = __fmul_rn(xi[k], xj[k]);
            float y = __fsub_rn(p, c);
            float t = __fadd_rn(s, y);
            c = __fsub_rn(__fsub_rn(t, s), y);
            s = t;
        }
        double d = (double)s + (double)c;
        #pragma unroll
        for (int o = 16; o; o >>= 1) d += __shfl_xor_sync(0xffffffffu, d, o);
        if (lane == 0) {
            float dotf = (float)d;
            float t1 = __fadd_rn(sqi, g_sq[j]);
            float t3 = fabsf(__fsub_rn(t1, __fmul_rn(2.0f, dotf)));
            keys[k4] = ((unsigned long long)__float_as_uint(t3) << 32) | (unsigned)j;
        }
    }
    __syncthreads();

    if (threadIdx.x == 0) {
        unsigned long long a[TK2];
        #pragma unroll
        for (int i = 0; i < TK2; i++) a[i] = keys[i];
        #pragma unroll
        for (int i = 1; i < TK2; i++) {
            unsigned long long v = a[i];
            int k = i - 1;
            while (k >= 0 && a[k] > v) { a[k + 1] = a[k]; k--; }
            a[k + 1] = v;
        }
        #pragma unroll
        for (int k = 0; k < TK; k++) g_idx[row * TK + k] = (int)(unsigned)a[k];
    }
}

// ---------------- 5. vertex degrees ----------------
__global__ void zero_cnt() {
    int t = blockIdx.x * 256 + threadIdx.x;
    if (t < NN) g_cnt[t] = 0;
}
__global__ void count_kernel() {
    int t = blockIdx.x * 256 + threadIdx.x;
    if (t < NN * TK) atomicAdd(&g_cnt[g_idx[t]], 1);
}
__global__ void dv_kernel() {
    int t = blockIdx.x * 256 + threadIdx.x;
    if (t < NN) g_dv[t] = 1.0f / sqrtf((float)g_cnt[t]);
}

// ---------------- zero fill ----------------
__global__ void zero_kernel(float4* __restrict__ p, size_t n4) {
    size_t t = (size_t)blockIdx.x * blockDim.x + threadIdx.x;
    size_t stride = (size_t)gridDim.x * blockDim.x;
    float4 z = make_float4(0.f, 0.f, 0.f, 0.f);
    for (size_t i = t; i < n4; i += stride) p[i] = z;
}

// ---------------- 6. H scatter: H[idx[i][k]][i] = 1 ----------------
__global__ void scatterH(float* __restrict__ H) {
    int t = blockIdx.x * 256 + threadIdx.x;
    if (t < NN * TK) {
        int i = t / TK;
        int r = g_idx[t];
        H[(size_t)r * NN + i] = 1.0f;
    }
}

// ---------------- 7. gather: G[i] = sum_k dv[idx]*X[idx] ----------------
__global__ __launch_bounds__(256) void gather_kernel(const float* __restrict__ X) {
    int i = blockIdx.x;
    __shared__ int   sidx[TK];
    __shared__ float sdv[TK];
    if (threadIdx.x < TK) {
        int r = g_idx[i * TK + threadIdx.x];
        sidx[threadIdx.x] = r;
        sdv[threadIdx.x]  = g_dv[r];
    }
    __syncthreads();
    for (int c = threadIdx.x; c < DF; c += 256) {
        float s = 0.f;
        #pragma unroll
        for (int k = 0; k < TK; k++)
            s = fmaf(sdv[k], X[(size_t)sidx[k] * DF + c], s);
        g_G[(size_t)i * DF + c] = s;
    }
}

// ---------------- 8. X_out = de * G @ theta   (M=8192, N=256, K=784) ----------------
#define BK 16
#define SPAD 4
__global__ __launch_bounds__(256) void out_gemm(const float* __restrict__ theta,
                                                float* __restrict__ Xout) {
    __shared__ float As[BK][64 + SPAD];
    __shared__ float Bs[BK][64 + SPAD];
    int tid = threadIdx.x;
    int tx = tid & 15, ty = tid >> 4;
    int bi = blockIdx.y * 64, bj = blockIdx.x * 64;

    float acc[4][4];
    #pragma unroll
    for (int m = 0; m < 4; m++)
        #pragma unroll
        for (int n = 0; n < 4; n++) acc[m][n] = 0.f;

    for (int k0 = 0; k0 < DF; k0 += BK) {
        {
            int row = tid >> 2, c4 = (tid & 3) * 4;
            float4 v = *reinterpret_cast<const float4*>(g_G + (size_t)(bi + row) * DF + k0 + c4);
            As[c4 + 0][row] = v.x; As[c4 + 1][row] = v.y;
            As[c4 + 2][row] = v.z; As[c4 + 3][row] = v.w;
            int kr = tid >> 4, n4 = (tid & 15) * 4;
            float4 w = *reinterpret_cast<const float4*>(theta + (size_t)(k0 + kr) * DEMB + bj + n4);
            Bs[kr][n4 + 0] = w.x; Bs[kr][n4 + 1] = w.y;
            Bs[kr][n4 + 2] = w.z; Bs[kr][n4 + 3] = w.w;
        }
        __syncthreads();
        #pragma unroll
        for (int kk = 0; kk < BK; kk++) {
            float a[4], b[4];
            #pragma unroll
            for (int m = 0; m < 4; m++) a[m] = As[kk][ty * 4 + m];
            #pragma unroll
            for (int n = 0; n < 4; n++) b[n] = Bs[kk][tx * 4 + n];
            #pragma unroll
            for (int m = 0; m < 4; m++)
                #pragma unroll
                for (int n = 0; n < 4; n++) acc[m][n] = fmaf(a[m], b[n], acc[m][n]);
        }
        __syncthreads();
    }
    const float de = 0.30151134457776363f;  // 11^-0.5
    #pragma unroll
    for (int m = 0; m < 4; m++) {
        int i = bi + ty * 4 + m;
        float4 o;
        o.x = de * acc[m][0]; o.y = de * acc[m][1];
        o.z = de * acc[m][2]; o.w = de * acc[m][3];
        *reinterpret_cast<float4*>(Xout + (size_t)i * DEMB + bj + tx * 4) = o;
    }
}

// ---------------- 9. E = dv * de * scatter-add of X_out ----------------
__global__ void scatterE(const float* __restrict__ Xout, float* __restrict__ E) {
    int j = blockIdx.x;
    int c = threadIdx.x;
    float v = Xout[(size_t)j * DEMB + c];
    #pragma unroll
    for (int k = 0; k < TK; k++) {
        int r = __ldg(&g_idx[j * TK + k]);
        atomicAdd(E + (size_t)r * DEMB + c, v);
    }
}
__global__ void scaleE(float* __restrict__ E) {
    int t = blockIdx.x * 256 + threadIdx.x;
    const float de = 0.30151134457776363f;
    int i = t >> 8;
    E[t] *= g_dv[i] * de;
}

// ---------------- launch ----------------
extern "C" void kernel_launch(void* const* d_in, const int* in_sizes, int n_in,
                              void* d_out, int out_size) {
    const float* X     = (const float*)d_in[0];
    const float* theta = (const float*)d_in[1];
    float* out  = (float*)d_out;
    float* Xout = out;                                // [8192, 256]
    float* E    = out + (size_t)NN * DEMB;            // [8192, 256]
    float* H    = out + 2 * (size_t)NN * DEMB;        // [8192, 8192] (dist scratch first)

    conv_kernel<<<NN, 256>>>(X);
    sq_kernel<<<NN / 8, 256>>>(X);
    dist_mma<<<dim3(NN / 128, NN / 128), 256>>>(H);       // bf16 HMMA coarse dist
    topk24_kernel<<<NN, 128>>>(H);
    refine_kernel<<<NN, 128>>>(X);                        // exact-emulated top-11
    zero_cnt<<<NN / 256, 256>>>();
    count_kernel<<<(NN * TK + 255) / 256, 256>>>();
    dv_kernel<<<NN / 256, 256>>>();
    zero_kernel<<<2048, 256>>>((float4*)H, (size_t)NN * NN / 4);
    scatterH<<<(NN * TK + 255) / 256, 256>>>(H);
    gather_kernel<<<NN, 256>>>(X);
    out_gemm<<<dim3(DEMB / 64, NN / 64), 256>>>(theta, Xout);
    zero_kernel<<<256, 256>>>((float4*)E, (size_t)NN * DEMB / 4);
    scatterE<<<NN, 256>>>(Xout, E);
    scaleE<<<NN * DEMB / 256, 256>>>(E);
}

// round 8
// speedup vs baseline: 2.7552x; 1.3790x over previous
#include <cuda_runtime.h>
#include <cuda_bf16.h>
#include <cstdint>
#include <cstddef>

#define NN   8192
#define DF   784
#define DFP  800     // padded K (25 * 32)
#define DEMB 256
#define TK   11
#define TK2  24      // coarse candidate count (margin >> bf16 coarse error)
#define NCB  64      // column blocks per row (NN / 128)
#define CAP  512     // survivor buffer capacity

// ---------------- scratch (static device globals; no allocs) ----------------
__device__ float g_sq[NN];                            // correctly-rounded fp32 row norms
__device__ __align__(16) __nv_bfloat16 g_Xb[(size_t)NN * DFP];  // bf16 X, zero-padded
__device__ float g_bmin[(size_t)NN * NCB];            // per-(row, colblock) min dist
__device__ int   g_idx24[NN * TK2];                   // coarse candidates
__device__ int   g_idx[NN * TK];                      // refined top-11
__device__ int   g_cnt[NN];
__device__ float g_dv[NN];
__device__ float g_G[(size_t)NN * DF];                // gathered dv-weighted rows

__device__ __forceinline__ unsigned smem_u32(const void* p) {
    return (unsigned)__cvta_generic_to_shared(p);
}

// ---------------- 0. convert X -> bf16 (zero-pad K to 800) ----------------
__global__ void conv_kernel(const float* __restrict__ X) {
    int row = blockIdx.x;
    for (int c = threadIdx.x; c < DFP; c += 256) {
        g_Xb[(size_t)row * DFP + c] =
            (c < DF) ? __float2bfloat16_rn(X[(size_t)row * DF + c]) : __float2bfloat16_rn(0.f);
    }
}

// ---------------- 1. row squared norms (correctly rounded) ----------------
__global__ void sq_kernel(const float* __restrict__ X) {
    int row  = blockIdx.x * 8 + (threadIdx.x >> 5);
    int lane = threadIdx.x & 31;
    const float* xr = X + (size_t)row * DF;
    float s = 0.f, c = 0.f;
    for (int k = lane; k < DF; k += 32) {
        float v = xr[k];
        float p = __fmul_rn(v, v);
        float y = __fsub_rn(p, c);
        float t = __fadd_rn(s, y);
        c = __fsub_rn(__fsub_rn(t, s), y);
        s = t;
    }
    double d = (double)s + (double)c;
    #pragma unroll
    for (int o = 16; o; o >>= 1) d += __shfl_xor_sync(0xffffffffu, d, o);
    if (lane == 0) g_sq[row] = (float)d;
}

// ---------------- 2. coarse dist via bf16 tensor cores + per-row block-min ----------------
// C = Xb @ Xb^T ; D[i][j] = |sq_i + sq_j - 2 C[i][j]| ; g_bmin[i][bx] = min_j-in-block D
#define SROW 40   // smem row stride in bf16 elems (80 B -> conflict-free ldmatrix)

__global__ __launch_bounds__(256) void dist_mma(float* __restrict__ D) {
    __shared__ __nv_bfloat16 As[128 * SROW];
    __shared__ __nv_bfloat16 Bs[128 * SROW];
    __shared__ float swm[128][4];

    int tid  = threadIdx.x;
    int warp = tid >> 5, lane = tid & 31;
    int bi = blockIdx.y * 128, bj = blockIdx.x * 128;
    int wm = (warp >> 2) * 64;     // 0 / 64
    int wn = (warp & 3) * 32;      // 0 / 32 / 64 / 96

    float acc[4][4][4];
    #pragma unroll
    for (int m = 0; m < 4; m++)
        #pragma unroll
        for (int n = 0; n < 4; n++)
            #pragma unroll
            for (int r = 0; r < 4; r++) acc[m][n][r] = 0.f;

    for (int kt = 0; kt < DFP / 32; kt++) {
        #pragma unroll
        for (int l = 0; l < 2; l++) {
            int q = tid + l * 256;
            int row = q >> 2, ch = q & 3;
            const int4* sa = (const int4*)(g_Xb + (size_t)(bi + row) * DFP + kt * 32 + ch * 8);
            *(int4*)(As + row * SROW + ch * 8) = *sa;
            const int4* sb = (const int4*)(g_Xb + (size_t)(bj + row) * DFP + kt * 32 + ch * 8);
            *(int4*)(Bs + row * SROW + ch * 8) = *sb;
        }
        __syncthreads();

        #pragma unroll
        for (int ks = 0; ks < 2; ks++) {
            int k0 = ks * 16;
            uint32_t a[4][4];
            #pragma unroll
            for (int mt = 0; mt < 4; mt++) {
                unsigned ad = smem_u32(As + (wm + mt * 16 + (lane & 15)) * SROW
                                          + k0 + ((lane >> 4) << 3));
                asm volatile("ldmatrix.sync.aligned.m8n8.x4.shared.b16 {%0,%1,%2,%3}, [%4];"
                             : "=r"(a[mt][0]), "=r"(a[mt][1]), "=r"(a[mt][2]), "=r"(a[mt][3])
                             : "r"(ad));
            }
            uint32_t b[4][2];
            #pragma unroll
            for (int bt = 0; bt < 2; bt++) {
                int nloc = wn + bt * 16 + ((lane >> 4) << 3) + (lane & 7);
                unsigned ad = smem_u32(Bs + nloc * SROW + k0 + (((lane >> 3) & 1) << 3));
                uint32_t r0, r1, r2, r3;
                asm volatile("ldmatrix.sync.aligned.m8n8.x4.shared.b16 {%0,%1,%2,%3}, [%4];"
                             : "=r"(r0), "=r"(r1), "=r"(r2), "=r"(r3) : "r"(ad));
                b[2 * bt][0] = r0; b[2 * bt][1] = r1;
                b[2 * bt + 1][0] = r2; b[2 * bt + 1][1] = r3;
            }
            #pragma unroll
            for (int mt = 0; mt < 4; mt++)
                #pragma unroll
                for (int nt = 0; nt < 4; nt++) {
                    asm volatile(
                        "mma.sync.aligned.m16n8k16.row.col.f32.bf16.bf16.f32 "
                        "{%0,%1,%2,%3}, {%4,%5,%6,%7}, {%8,%9}, {%0,%1,%2,%3};"
                        : "+f"(acc[mt][nt][0]), "+f"(acc[mt][nt][1]),
                          "+f"(acc[mt][nt][2]), "+f"(acc[mt][nt][3])
                        : "r"(a[mt][0]), "r"(a[mt][1]), "r"(a[mt][2]), "r"(a[mt][3]),
                          "r"(b[nt][0]), "r"(b[nt][1]));
                }
        }
        __syncthreads();
    }

    // epilogue: dist = |sq_i + sq_j - 2*acc| ; also per-row min over this block
    int r_in = lane >> 2, cb = (lane & 3) * 2;
    #pragma unroll
    for (int mt = 0; mt < 4; mt++) {
        #pragma unroll
        for (int half = 0; half < 2; half++) {
            int gi = bi + wm + mt * 16 + r_in + half * 8;
            float sqi = g_sq[gi];
            float rmin = 3.4e38f;
            #pragma unroll
            for (int nt = 0; nt < 4; nt++) {
                int gj = bj + wn + nt * 8 + cb;
                float2 o;
                o.x = fabsf(sqi + g_sq[gj]     - 2.f * acc[mt][nt][half * 2 + 0]);
                o.y = fabsf(sqi + g_sq[gj + 1] - 2.f * acc[mt][nt][half * 2 + 1]);
                rmin = fminf(rmin, fminf(o.x, o.y));
                *reinterpret_cast<float2*>(D + (size_t)gi * NN + gj) = o;
            }
            rmin = fminf(rmin, __shfl_xor_sync(0xffffffffu, rmin, 1));
            rmin = fminf(rmin, __shfl_xor_sync(0xffffffffu, rmin, 2));
            if ((lane & 3) == 0)
                swm[wm + mt * 16 + r_in + half * 8][warp & 3] = rmin;
        }
    }
    __syncthreads();
    if (tid < 128) {
        float m = fminf(fminf(swm[tid][0], swm[tid][1]),
                        fminf(swm[tid][2], swm[tid][3]));
        g_bmin[(size_t)(bi + tid) * NCB + blockIdx.x] = m;
    }
}

// ---------------- 3. per-row top-24 via threshold filter ----------------
// T = 24th smallest of the row's 64 block-mins (each an actual row value at a
// distinct position => valid upper bound on the 24th order statistic).
__global__ __launch_bounds__(256) void topk_fast(const float* __restrict__ D) {
    int row = blockIdx.x, t = threadIdx.x;
    __shared__ float sb[NCB];
    __shared__ float sT;
    __shared__ int cnt;
    __shared__ unsigned long long buf[CAP];

    if (t < NCB) sb[t] = g_bmin[(size_t)row * NCB + t];
    if (t == 0) cnt = 0;
    __syncthreads();

    if (t == 0) {
        float best[TK2];
        #pragma unroll
        for (int k = 0; k < TK2; k++) best[k] = 3.4e38f;
        for (int i = 0; i < NCB; i++) {
            float x = sb[i];
            if (x < best[TK2 - 1]) {
                int k = TK2 - 1;
                while (k > 0 && best[k - 1] > x) { best[k] = best[k - 1]; k--; }
                best[k] = x;
            }
        }
        sT = best[TK2 - 1];
    }
    __syncthreads();
    float T = sT;

    const float4* dr4 = (const float4*)(D + (size_t)row * NN);
    #pragma unroll
    for (int i = 0; i < 8; i++) {
        int v4 = t + i * 256;
        float4 w = dr4[v4];
        int j0 = v4 * 4;
        float vals[4] = {w.x, w.y, w.z, w.w};
        #pragma unroll
        for (int q = 0; q < 4; q++) {
            if (vals[q] <= T) {
                int p = atomicAdd(&cnt, 1);
                if (p < CAP)
                    buf[p] = ((unsigned long long)__float_as_uint(vals[q]) << 32)
                             | (unsigned)(j0 + q);
            }
        }
    }
    __syncthreads();

    if (t == 0) {
        unsigned long long best[TK2];
        #pragma unroll
        for (int k = 0; k < TK2; k++) best[k] = ~0ull;
        if (cnt <= CAP) {
            int n = cnt;
            for (int i = 0; i < n; i++) {
                unsigned long long x = buf[i];
                if (x < best[TK2 - 1]) {
                    int k = TK2 - 1;
                    while (k > 0 && best[k - 1] > x) { best[k] = best[k - 1]; k--; }
                    best[k] = x;
                }
            }
        } else {
            // fallback (practically unreachable): full serial scan, still exact
            const float* dr = D + (size_t)row * NN;
            for (int j = 0; j < NN; j++) {
                unsigned long long x =
                    ((unsigned long long)__float_as_uint(dr[j]) << 32) | (unsigned)j;
                if (x < best[TK2 - 1]) {
                    int k = TK2 - 1;
                    while (k > 0 && best[k - 1] > x) { best[k] = best[k - 1]; k--; }
                    best[k] = x;
                }
            }
        }
        #pragma unroll
        for (int k = 0; k < TK2; k++) g_idx24[row * TK2 + k] = (int)(unsigned)best[k];
    }
}

// ---------------- 4. refine: exact dists with ref's rounding chain, pick top-11 ----------------
__global__ __launch_bounds__(128) void refine_kernel(const float* __restrict__ X) {
    int row = blockIdx.x;
    int wid = threadIdx.x >> 5, lane = threadIdx.x & 31;
    __shared__ unsigned long long keys[TK2];
    __shared__ int cand[TK2];
    if (threadIdx.x < TK2) cand[threadIdx.x] = g_idx24[row * TK2 + threadIdx.x];
    __syncthreads();

    float sqi = g_sq[row];
    const float* xi = X + (size_t)row * DF;

    for (int k4 = wid; k4 < TK2; k4 += 4) {
        int j = cand[k4];
        const float* xj = X + (size_t)j * DF;
        float s = 0.f, c = 0.f;
        for (int k = lane; k < DF; k += 32) {
            float p = __fmul_rn(xi[k], xj[k]);
            float y = __fsub_rn(p, c);
            float t = __fadd_rn(s, y);
            c = __fsub_rn(__fsub_rn(t, s), y);
            s = t;
        }
        double d = (double)s + (double)c;
        #pragma unroll
        for (int o = 16; o; o >>= 1) d += __shfl_xor_sync(0xffffffffu, d, o);
        if (lane == 0) {
            float dotf = (float)d;
            float t1 = __fadd_rn(sqi, g_sq[j]);
            float t3 = fabsf(__fsub_rn(t1, __fmul_rn(2.0f, dotf)));
            keys[k4] = ((unsigned long long)__float_as_uint(t3) << 32) | (unsigned)j;
        }
    }
    __syncthreads();

    if (threadIdx.x == 0) {
        unsigned long long a[TK2];
        #pragma unroll
        for (int i = 0; i < TK2; i++) a[i] = keys[i];
        #pragma unroll
        for (int i = 1; i < TK2; i++) {
            unsigned long long v = a[i];
            int k = i - 1;
            while (k >= 0 && a[k] > v) { a[k + 1] = a[k]; k--; }
            a[k + 1] = v;
        }
        #pragma unroll
        for (int k = 0; k < TK; k++) g_idx[row * TK + k] = (int)(unsigned)a[k];
    }
}

// ---------------- 5. vertex degrees ----------------
__global__ void zero_cnt() {
    int t = blockIdx.x * 256 + threadIdx.x;
    if (t < NN) g_cnt[t] = 0;
}
__global__ void count_kernel() {
    int t = blockIdx.x * 256 + threadIdx.x;
    if (t < NN * TK) atomicAdd(&g_cnt[g_idx[t]], 1);
}
__global__ void dv_kernel() {
    int t = blockIdx.x * 256 + threadIdx.x;
    if (t < NN) g_dv[t] = 1.0f / sqrtf((float)g_cnt[t]);
}

// ---------------- zero fill ----------------
__global__ void zero_kernel(float4* __restrict__ p, size_t n4) {
    size_t t = (size_t)blockIdx.x * blockDim.x + threadIdx.x;
    size_t stride = (size_t)gridDim.x * blockDim.x;
    float4 z = make_float4(0.f, 0.f, 0.f, 0.f);
    for (size_t i = t; i < n4; i += stride) p[i] = z;
}

// ---------------- 6. H scatter: H[idx[i][k]][i] = 1 ----------------
__global__ void scatterH(float* __restrict__ H) {
    int t = blockIdx.x * 256 + threadIdx.x;
    if (t < NN * TK) {
        int i = t / TK;
        int r = g_idx[t];
        H[(size_t)r * NN + i] = 1.0f;
    }
}

// ---------------- 7. gather: G[i] = sum_k dv[idx]*X[idx] ----------------
__global__ __launch_bounds__(256) void gather_kernel(const float* __restrict__ X) {
    int i = blockIdx.x;
    __shared__ int   sidx[TK];
    __shared__ float sdv[TK];
    if (threadIdx.x < TK) {
        int r = g_idx[i * TK + threadIdx.x];
        sidx[threadIdx.x] = r;
        sdv[threadIdx.x]  = g_dv[r];
    }
    __syncthreads();
    for (int c = threadIdx.x; c < DF; c += 256) {
        float s = 0.f;
        #pragma unroll
        for (int k = 0; k < TK; k++)
            s = fmaf(sdv[k], X[(size_t)sidx[k] * DF + c], s);
        g_G[(size_t)i * DF + c] = s;
    }
}

// ---------------- 8. X_out = de * G @ theta   (M=8192, N=256, K=784) ----------------
#define BK 16
#define SPAD 4
__global__ __launch_bounds__(256) void out_gemm(const float* __restrict__ theta,
                                                float* __restrict__ Xout) {
    __shared__ float As[BK][64 + SPAD];
    __shared__ float Bs[BK][64 + SPAD];
    int tid = threadIdx.x;
    int tx = tid & 15, ty = tid >> 4;
    int bi = blockIdx.y * 64, bj = blockIdx.x * 64;

    float acc[4][4];
    #pragma unroll
    for (int m = 0; m < 4; m++)
        #pragma unroll
        for (int n = 0; n < 4; n++) acc[m][n] = 0.f;

    for (int k0 = 0; k0 < DF; k0 += BK) {
        {
            int row = tid >> 2, c4 = (tid & 3) * 4;
            float4 v = *reinterpret_cast<const float4*>(g_G + (size_t)(bi + row) * DF + k0 + c4);
            As[c4 + 0][row] = v.x; As[c4 + 1][row] = v.y;
            As[c4 + 2][row] = v.z; As[c4 + 3][row] = v.w;
            int kr = tid >> 4, n4 = (tid & 15) * 4;
            float4 w = *reinterpret_cast<const float4*>(theta + (size_t)(k0 + kr) * DEMB + bj + n4);
            Bs[kr][n4 + 0] = w.x; Bs[kr][n4 + 1] = w.y;
            Bs[kr][n4 + 2] = w.z; Bs[kr][n4 + 3] = w.w;
        }
        __syncthreads();
        #pragma unroll
        for (int kk = 0; kk < BK; kk++) {
            float a[4], b[4];
            #pragma unroll
            for (int m = 0; m < 4; m++) a[m] = As[kk][ty * 4 + m];
            #pragma unroll
            for (int n = 0; n < 4; n++) b[n] = Bs[kk][tx * 4 + n];
            #pragma unroll
            for (int m = 0; m < 4; m++)
                #pragma unroll
                for (int n = 0; n < 4; n++) acc[m][n] = fmaf(a[m], b[n], acc[m][n]);
        }
        __syncthreads();
    }
    const float de = 0.30151134457776363f;  // 11^-0.5
    #pragma unroll
    for (int m = 0; m < 4; m++) {
        int i = bi + ty * 4 + m;
        float4 o;
        o.x = de * acc[m][0]; o.y = de * acc[m][1];
        o.z = de * acc[m][2]; o.w = de * acc[m][3];
        *reinterpret_cast<float4*>(Xout + (size_t)i * DEMB + bj + tx * 4) = o;
    }
}

// ---------------- 9. E = dv * de * scatter-add of X_out ----------------
__global__ void scatterE(const float* __restrict__ Xout, float* __restrict__ E) {
    int j = blockIdx.x;
    int c = threadIdx.x;
    float v = Xout[(size_t)j * DEMB + c];
    #pragma unroll
    for (int k = 0; k < TK; k++) {
        int r = __ldg(&g_idx[j * TK + k]);
        atomicAdd(E + (size_t)r * DEMB + c, v);
    }
}
__global__ void scaleE(float* __restrict__ E) {
    int t = blockIdx.x * 256 + threadIdx.x;
    const float de = 0.30151134457776363f;
    int i = t >> 8;
    E[t] *= g_dv[i] * de;
}

// ---------------- launch ----------------
extern "C" void kernel_launch(void* const* d_in, const int* in_sizes, int n_in,
                              void* d_out, int out_size) {
    const float* X     = (const float*)d_in[0];
    const float* theta = (const float*)d_in[1];
    float* out  = (float*)d_out;
    float* Xout = out;                                // [8192, 256]
    float* E    = out + (size_t)NN * DEMB;            // [8192, 256]
    float* H    = out + 2 * (size_t)NN * DEMB;        // [8192, 8192] (dist scratch first)

    conv_kernel<<<NN, 256>>>(X);
    sq_kernel<<<NN / 8, 256>>>(X);
    dist_mma<<<dim3(NN / 128, NN / 128), 256>>>(H);       // bf16 HMMA coarse dist + blockmins
    topk_fast<<<NN, 256>>>(H);
    refine_kernel<<<NN, 128>>>(X);                        // exact-emulated top-11
    zero_cnt<<<NN / 256, 256>>>();
    count_kernel<<<(NN * TK + 255) / 256, 256>>>();
    dv_kernel<<<NN / 256, 256>>>();
    zero_kernel<<<2048, 256>>>((float4*)H, (size_t)NN * NN / 4);
    scatterH<<<(NN * TK + 255) / 256, 256>>>(H);
    gather_kernel<<<NN, 256>>>(X);
    out_gemm<<<dim3(DEMB / 64, NN / 64), 256>>>(theta, Xout);
    zero_kernel<<<256, 256>>>((float4*)E, (size_t)NN * DEMB / 4);
    scatterE<<<NN, 256>>>(Xout, E);
    scaleE<<<NN * DEMB / 256, 256>>>(E);
}